// round 1
// baseline (speedup 1.0000x reference)
#include <cuda_runtime.h>
#include <math.h>

// Problem constants: B=4, C=64, H=W=64, P=4096.
#define BATCH 4
#define CCH 64
#define PPIX 4096
#define PADK 68   // sK / sP row stride (floats); 68*4B=272B keeps float4 alignment, spreads banks

// Scratch (device globals; no allocation allowed).
__device__ float g_K[BATCH * CCH * PPIX];   // normalized kernels, [b][c][p]
__device__ float g_Y[BATCH * CCH * PPIX];   // 3x3 zero-padded box sum,  [b][c][p]

// ---------------------------------------------------------------------------
// prep: per (b,p) compute inv-norm over channels, write Knorm and box-sum Y.
// grid (16, 4): 4 rows h per block; block 256 = 4 rows x 64 w.
// ---------------------------------------------------------------------------
__global__ void __launch_bounds__(256) prep_kernel(const float* __restrict__ f) {
    const int b  = blockIdx.y;
    const int hs = threadIdx.x >> 6;            // 0..3
    const int w  = threadIdx.x & 63;
    const int h  = (blockIdx.x << 2) + hs;
    __shared__ float sv[4][68];                 // vertical 3-sum per row, zero-padded [0],[65]

    if (w == 0) { sv[hs][0] = 0.f; sv[hs][65] = 0.f; }

    const float* fb = f + b * (CCH * PPIX);
    const int p = h * 64 + w;
    float sumsq = 0.f;

    for (int c = 0; c < CCH; ++c) {
        const float* fr = fb + c * PPIX + p;
        float r1 = fr[0];
        float r0 = (h > 0)  ? fr[-64] : 0.f;
        float r2 = (h < 63) ? fr[64]  : 0.f;
        sumsq += r1 * r1;
        __syncthreads();                        // protect prev-iter reads of sv
        sv[hs][w + 1] = r0 + r1 + r2;
        __syncthreads();
        g_Y[(b * CCH + c) * PPIX + p] = sv[hs][w] + sv[hs][w + 1] + sv[hs][w + 2];
    }

    const float inv = 1.f / (sqrtf(sumsq) + 1e-8f);
    for (int c = 0; c < CCH; ++c)
        g_K[(b * CCH + c) * PPIX + p] = fb[c * PPIX + p] * inv;
}

// ---------------------------------------------------------------------------
// Fused attention: out[b,c,q] = sum_p softmax_p(K[p]·Y[q]) * K[p,c]
// CTA = (q-tile of 64, batch). 256 threads; thread (tx,ty) owns rows q=ty*4+i,
// cols {tx+16j}. Online softmax over 64 key tiles of 64.
// ---------------------------------------------------------------------------
__global__ void __launch_bounds__(256) attn_kernel(float* __restrict__ out) {
    extern __shared__ float smem[];
    float* sQ = smem;                    // [64][64]   (c-major: sQ[c][q])
    float* sK = sQ + 64 * 64;            // [64][PADK] (sK[c][k])
    float* sP = sK + 64 * PADK;          // [64][PADK] (sP[q][k]; reused as [c][q] in epilogue)
    float* smx = sP + 64 * PADK;         // [64] running max
    float* sl  = smx + 64;               // [64] running denom

    const int b  = blockIdx.y;
    const int q0 = blockIdx.x * 64;
    const int t  = threadIdx.x;
    const int tx = t & 15, ty = t >> 4;

    const float* Yb = g_Y + b * (CCH * PPIX);
    const float* Kb = g_K + b * (CCH * PPIX);

    // Load Q tile (Y) as [c][q]
    for (int i = t; i < 64 * 16; i += 256) {
        int row = i >> 4, f4 = i & 15;
        ((float4*)(sQ + row * 64))[f4] = ((const float4*)(Yb + row * PPIX + q0))[f4];
    }
    if (t < 64) { smx[t] = -INFINITY; sl[t] = 0.f; }

    float o[4][4];
    #pragma unroll
    for (int i = 0; i < 4; ++i)
        #pragma unroll
        for (int j = 0; j < 4; ++j) o[i][j] = 0.f;

    __syncthreads();

    for (int k0 = 0; k0 < PPIX; k0 += 64) {
        // Load K tile [c][k]
        for (int i = t; i < 64 * 16; i += 256) {
            int row = i >> 4, f4 = i & 15;
            ((float4*)(sK + row * PADK))[f4] = ((const float4*)(Kb + row * PPIX + k0))[f4];
        }
        __syncthreads();

        // S[q][k] = sum_c sQ[c][q] * sK[c][k]
        float s[4][4];
        #pragma unroll
        for (int i = 0; i < 4; ++i)
            #pragma unroll
            for (int j = 0; j < 4; ++j) s[i][j] = 0.f;

        #pragma unroll 8
        for (int c = 0; c < 64; ++c) {
            float4 av = *(const float4*)(sQ + c * 64 + ty * 4);
            float a[4] = {av.x, av.y, av.z, av.w};
            float bk[4];
            bk[0] = sK[c * PADK + tx];
            bk[1] = sK[c * PADK + tx + 16];
            bk[2] = sK[c * PADK + tx + 32];
            bk[3] = sK[c * PADK + tx + 48];
            #pragma unroll
            for (int i = 0; i < 4; ++i)
                #pragma unroll
                for (int j = 0; j < 4; ++j)
                    s[i][j] = fmaf(a[i], bk[j], s[i][j]);
        }

        // Online softmax update (rows shared by a half-warp: lanes with same ty)
        float mn[4], corr[4], rs[4];
        #pragma unroll
        for (int i = 0; i < 4; ++i) {
            float rm = fmaxf(fmaxf(s[i][0], s[i][1]), fmaxf(s[i][2], s[i][3]));
            #pragma unroll
            for (int off = 1; off < 16; off <<= 1)
                rm = fmaxf(rm, __shfl_xor_sync(0xffffffffu, rm, off));
            float mo = smx[ty * 4 + i];
            mn[i]   = fmaxf(mo, rm);
            corr[i] = __expf(mo - mn[i]);
            float sum = 0.f;
            #pragma unroll
            for (int j = 0; j < 4; ++j) {
                float pv = __expf(s[i][j] - mn[i]);
                sP[(ty * 4 + i) * PADK + tx + 16 * j] = pv;
                sum += pv;
            }
            #pragma unroll
            for (int off = 1; off < 16; off <<= 1)
                sum += __shfl_xor_sync(0xffffffffu, sum, off);
            rs[i] = sum;
            #pragma unroll
            for (int j = 0; j < 4; ++j) o[i][j] *= corr[i];
        }
        __syncthreads();   // all smx reads done, sP visible
        if (tx == 0) {
            #pragma unroll
            for (int i = 0; i < 4; ++i) {
                int r = ty * 4 + i;
                smx[r] = mn[i];
                sl[r]  = sl[r] * corr[i] + rs[i];
            }
        }

        // O[q][c] += sum_k sP[q][k] * sK[c][k]
        #pragma unroll 2
        for (int k = 0; k < 64; k += 4) {
            float4 a0 = *(const float4*)(sP + (ty * 4 + 0) * PADK + k);
            float4 a1 = *(const float4*)(sP + (ty * 4 + 1) * PADK + k);
            float4 a2 = *(const float4*)(sP + (ty * 4 + 2) * PADK + k);
            float4 a3 = *(const float4*)(sP + (ty * 4 + 3) * PADK + k);
            float4 v0 = *(const float4*)(sK + (tx)      * PADK + k);
            float4 v1 = *(const float4*)(sK + (tx + 16) * PADK + k);
            float4 v2 = *(const float4*)(sK + (tx + 32) * PADK + k);
            float4 v3 = *(const float4*)(sK + (tx + 48) * PADK + k);
            o[0][0] += a0.x*v0.x + a0.y*v0.y + a0.z*v0.z + a0.w*v0.w;
            o[0][1] += a0.x*v1.x + a0.y*v1.y + a0.z*v1.z + a0.w*v1.w;
            o[0][2] += a0.x*v2.x + a0.y*v2.y + a0.z*v2.z + a0.w*v2.w;
            o[0][3] += a0.x*v3.x + a0.y*v3.y + a0.z*v3.z + a0.w*v3.w;
            o[1][0] += a1.x*v0.x + a1.y*v0.y + a1.z*v0.z + a1.w*v0.w;
            o[1][1] += a1.x*v1.x + a1.y*v1.y + a1.z*v1.z + a1.w*v1.w;
            o[1][2] += a1.x*v2.x + a1.y*v2.y + a1.z*v2.z + a1.w*v2.w;
            o[1][3] += a1.x*v3.x + a1.y*v3.y + a1.z*v3.z + a1.w*v3.w;
            o[2][0] += a2.x*v0.x + a2.y*v0.y + a2.z*v0.z + a2.w*v0.w;
            o[2][1] += a2.x*v1.x + a2.y*v1.y + a2.z*v1.z + a2.w*v1.w;
            o[2][2] += a2.x*v2.x + a2.y*v2.y + a2.z*v2.z + a2.w*v2.w;
            o[2][3] += a2.x*v3.x + a2.y*v3.y + a2.z*v3.z + a2.w*v3.w;
            o[3][0] += a3.x*v0.x + a3.y*v0.y + a3.z*v0.z + a3.w*v0.w;
            o[3][1] += a3.x*v1.x + a3.y*v1.y + a3.z*v1.z + a3.w*v1.w;
            o[3][2] += a3.x*v2.x + a3.y*v2.y + a3.z*v2.z + a3.w*v2.w;
            o[3][3] += a3.x*v3.x + a3.y*v3.y + a3.z*v3.z + a3.w*v3.w;
        }
        __syncthreads();   // before sK/sP overwrite; also publishes smx/sl updates
    }

    // Normalize and write out[b][c][q] (transpose through sP for coalesced stores)
    float invl[4];
    #pragma unroll
    for (int i = 0; i < 4; ++i) invl[i] = 1.f / sl[ty * 4 + i];
    #pragma unroll
    for (int i = 0; i < 4; ++i)
        #pragma unroll
        for (int j = 0; j < 4; ++j)
            sP[(tx + 16 * j) * PADK + ty * 4 + i] = o[i][j] * invl[i];
    __syncthreads();

    float* ob = out + b * (CCH * PPIX);
    for (int i = t; i < 64 * 16; i += 256) {
        int row = i >> 4, f4 = i & 15;
        ((float4*)(ob + row * PPIX + q0))[f4] = ((const float4*)(sP + row * PADK))[f4];
    }
}

// ---------------------------------------------------------------------------
extern "C" void kernel_launch(void* const* d_in, const int* in_sizes, int n_in,
                              void* d_out, int out_size) {
    const float* f = (const float*)d_in[0];   // foreground [4,64,64,64] fp32
    // d_in[1] (masks) is unused on the reference's first-call path.
    float* out = (float*)d_out;               // [4,64,64,64] fp32

    prep_kernel<<<dim3(16, 4), 256>>>(f);

    const int smem_bytes = (64 * 64 + 2 * 64 * PADK + 128) * (int)sizeof(float); // ~51.7 KB
    cudaFuncSetAttribute(attn_kernel, cudaFuncAttributeMaxDynamicSharedMemorySize, smem_bytes);
    attn_kernel<<<dim3(64, 4), 256, smem_bytes>>>(out);
}

// round 3
// speedup vs baseline: 2.4040x; 2.4040x over previous
#include <cuda_runtime.h>
#include <cuda_bf16.h>
#include <stdint.h>
#include <math.h>

// Problem constants: B=4, C=64, H=W=64, P=4096.
#define BATCH 4
#define CCH   64
#define PPIX  4096
#define LOG2E 1.4426950408889634f

// ---------------------------------------------------------------------------
// Device scratch (no allocation allowed). Split bf16: x = hi + lo (~16 bits).
// ---------------------------------------------------------------------------
__device__ __nv_bfloat16 g_Qh[BATCH * PPIX * CCH];  // Y boxsum  [b][p][c]
__device__ __nv_bfloat16 g_Ql[BATCH * PPIX * CCH];
__device__ __nv_bfloat16 g_Kh[BATCH * PPIX * CCH];  // K-hat     [b][p][c]
__device__ __nv_bfloat16 g_Kl[BATCH * PPIX * CCH];
__device__ float         g_m [BATCH * PPIX];        // |Y_q| (softmax max bound)

// ---------------------------------------------------------------------------
// helpers (baseline PTX only: mma.sync / ldmatrix / cp.async — no "a" features)
// ---------------------------------------------------------------------------
__device__ __forceinline__ uint32_t smem_u32(const void* p) {
    uint32_t a;
    asm("{ .reg .u64 t; cvta.to.shared.u64 t, %1; cvt.u32.u64 %0, t; }" : "=r"(a) : "l"(p));
    return a;
}
__device__ __forceinline__ uint32_t lds32(uint32_t a) {
    uint32_t v; asm volatile("ld.shared.b32 %0, [%1];" : "=r"(v) : "r"(a)); return v;
}
__device__ __forceinline__ void ldsm4t(uint32_t* r, uint32_t addr) {
    asm volatile("ldmatrix.sync.aligned.m8n8.x4.trans.shared.b16 {%0,%1,%2,%3}, [%4];"
        : "=r"(r[0]), "=r"(r[1]), "=r"(r[2]), "=r"(r[3]) : "r"(addr));
}
__device__ __forceinline__ void mma16816(float* d, const uint32_t* a, uint32_t b0, uint32_t b1) {
    asm volatile(
        "mma.sync.aligned.m16n8k16.row.col.f32.bf16.bf16.f32 "
        "{%0,%1,%2,%3}, {%4,%5,%6,%7}, {%8,%9}, {%0,%1,%2,%3};"
        : "+f"(d[0]), "+f"(d[1]), "+f"(d[2]), "+f"(d[3])
        : "r"(a[0]), "r"(a[1]), "r"(a[2]), "r"(a[3]), "r"(b0), "r"(b1));
}
__device__ __forceinline__ float ex2(float x) {
    float r; asm("ex2.approx.ftz.f32 %0, %1;" : "=f"(r) : "f"(x)); return r;
}
__device__ __forceinline__ void split_bf16(float x, __nv_bfloat16& h, __nv_bfloat16& l) {
    h = __float2bfloat16_rn(x);
    l = __float2bfloat16_rn(x - __bfloat162float(h));
}
__device__ __forceinline__ void split2(float p0, float p1, uint32_t& hp, uint32_t& lp) {
    __nv_bfloat16 h0, l0, h1, l1;
    split_bf16(p0, h0, l0);
    split_bf16(p1, h1, l1);
    hp = (uint32_t)__bfloat16_as_ushort(h0) | ((uint32_t)__bfloat16_as_ushort(h1) << 16);
    lp = (uint32_t)__bfloat16_as_ushort(l0) | ((uint32_t)__bfloat16_as_ushort(l1) << 16);
}

// K tile smem geometry: [128 k][64 c] bf16, row pitch 144B (128B data + 16B pad)
#define KPITCH    144
#define TILE_H    18432            // 128 * 144
#define BUF_BYTES 36864            // hi + lo
#define SMEM_TOTAL 73728           // two buffers

__device__ __forceinline__ void load_tile(uint32_t dbuf,
                                          const __nv_bfloat16* gKh,
                                          const __nv_bfloat16* gKl,
                                          int k0, int t) {
    #pragma unroll
    for (int c = 0; c < 4; ++c) {
        int idx = t + 256 * c;                 // 0..1023
        int row = idx >> 3, ch = idx & 7;
        uint32_t d = dbuf + row * KPITCH + ch * 16;
        const void* sh = gKh + (size_t)(k0 + row) * CCH + ch * 8;
        const void* sl = gKl + (size_t)(k0 + row) * CCH + ch * 8;
        asm volatile("cp.async.cg.shared.global [%0], [%1], 16;" :: "r"(d), "l"(sh));
        asm volatile("cp.async.cg.shared.global [%0], [%1], 16;" :: "r"(d + TILE_H), "l"(sl));
    }
}

// ---------------------------------------------------------------------------
// prep: per (b,p): boxsum Y, K-hat, bf16 hi/lo splits, m = |Y|_2.
// ---------------------------------------------------------------------------
__global__ void __launch_bounds__(256) prep_kernel(const float* __restrict__ f) {
    const int b  = blockIdx.y;
    const int hs = threadIdx.x >> 6;
    const int w  = threadIdx.x & 63;
    const int h  = (blockIdx.x << 2) + hs;
    __shared__ float sv[4][68];
    if (w == 0) { sv[hs][0] = 0.f; sv[hs][65] = 0.f; }

    const float* fb = f + b * (CCH * PPIX);
    const int p = h * 64 + w;
    const int rowbase = (b * PPIX + p) * CCH;
    float fsq = 0.f, ysq = 0.f;

    for (int c = 0; c < CCH; ++c) {
        const float* fr = fb + c * PPIX + p;
        float r1 = fr[0];
        float r0 = (h > 0)  ? fr[-64] : 0.f;
        float r2 = (h < 63) ? fr[64]  : 0.f;
        fsq += r1 * r1;
        __syncthreads();
        sv[hs][w + 1] = r0 + r1 + r2;
        __syncthreads();
        float y = sv[hs][w] + sv[hs][w + 1] + sv[hs][w + 2];
        ysq += y * y;
        __nv_bfloat16 yh, yl; split_bf16(y, yh, yl);
        g_Qh[rowbase + c] = yh;
        g_Ql[rowbase + c] = yl;
    }

    g_m[b * PPIX + p] = sqrtf(ysq);
    const float inv = 1.f / (sqrtf(fsq) + 1e-8f);

    for (int c = 0; c < CCH; ++c) {
        float k = fb[c * PPIX + p] * inv;
        __nv_bfloat16 kh, kl; split_bf16(k, kh, kl);
        g_Kh[rowbase + c] = kh;
        g_Kl[rowbase + c] = kl;
    }
}

// ---------------------------------------------------------------------------
// attn: CTA = (128-q tile, batch), 256 threads = 8 warps as 4(q) x 2(k-split).
// Per key tile of 128: S = Q.K^T (3 split MMAs), p = exp2(S*log2e - m*log2e)
// with static max m=|Y| (no online rescale), O += P.K (3 split MMAs) with the
// P C-frag -> A-frag register identity. lsum/O reduced across the 2 k-warps
// only in the epilogue.
// ---------------------------------------------------------------------------
__global__ void __launch_bounds__(256, 1) attn_kernel(float* __restrict__ out) {
    extern __shared__ char smem[];
    const uint32_t sb = smem_u32(smem);

    const int b    = blockIdx.y;
    const int q0   = blockIdx.x * 128;
    const int t    = threadIdx.x;
    const int lane = t & 31;
    const int wid  = t >> 5;
    const int qi   = wid >> 1, kj = wid & 1;
    const int qo   = qi * 32,  ko = kj * 64;
    const int g    = lane >> 2, tq = lane & 3;

    // ---- persistent Q A-frags (hi/lo) + per-row max bounds ----
    uint32_t qa[2][2][4][4];
    #pragma unroll
    for (int hl = 0; hl < 2; ++hl) {
        const __nv_bfloat16* Qsrc = hl ? g_Ql : g_Qh;
        #pragma unroll
        for (int mi = 0; mi < 2; ++mi) {
            const __nv_bfloat16* r0 = Qsrc + (size_t)(b * PPIX + q0 + qo + 16 * mi + g) * CCH;
            const __nv_bfloat16* r8 = r0 + 8 * CCH;
            #pragma unroll
            for (int s = 0; s < 4; ++s) {
                int c0 = 16 * s + 2 * tq;
                qa[hl][mi][s][0] = *(const uint32_t*)(r0 + c0);
                qa[hl][mi][s][1] = *(const uint32_t*)(r8 + c0);
                qa[hl][mi][s][2] = *(const uint32_t*)(r0 + c0 + 8);
                qa[hl][mi][s][3] = *(const uint32_t*)(r8 + c0 + 8);
            }
        }
    }
    float mk[2][2];
    #pragma unroll
    for (int mi = 0; mi < 2; ++mi)
        #pragma unroll
        for (int h = 0; h < 2; ++h)
            mk[mi][h] = g_m[b * PPIX + q0 + qo + 16 * mi + 8 * h + g] * LOG2E;

    float oacc[2][8][4];
    #pragma unroll
    for (int mi = 0; mi < 2; ++mi)
        #pragma unroll
        for (int n = 0; n < 8; ++n)
            #pragma unroll
            for (int r = 0; r < 4; ++r) oacc[mi][n][r] = 0.f;
    float lsum[2][2] = {{0.f, 0.f}, {0.f, 0.f}};

    const __nv_bfloat16* gKh = g_Kh + (size_t)b * PPIX * CCH;
    const __nv_bfloat16* gKl = g_Kl + (size_t)b * PPIX * CCH;

    // prefetch tile 0
    load_tile(sb, gKh, gKl, 0, t);
    asm volatile("cp.async.commit_group;" ::: "memory");

    const uint32_t laneoff = (uint32_t)(((lane & 7) + 8 * ((lane >> 3) & 1)) * KPITCH
                                        + (lane >> 4) * 16);

    for (int kt = 0; kt < 32; ++kt) {
        __syncthreads();                                  // frees buf[(kt+1)&1]
        if (kt + 1 < 32)
            load_tile(sb + ((kt + 1) & 1) * BUF_BYTES, gKh, gKl, (kt + 1) * 128, t);
        asm volatile("cp.async.commit_group;" ::: "memory");
        asm volatile("cp.async.wait_group 1;" ::: "memory");
        __syncthreads();                                  // buf[kt&1] visible

        const uint32_t aH = sb + (uint32_t)(kt & 1) * BUF_BYTES;
        const uint32_t aL = aH + TILE_H;

        // ---- S = Q.K^T over this warp's 64-key slice ----
        float sacc[2][8][4];
        #pragma unroll
        for (int mi = 0; mi < 2; ++mi)
            #pragma unroll
            for (int j = 0; j < 8; ++j)
                #pragma unroll
                for (int r = 0; r < 4; ++r) sacc[mi][j][r] = 0.f;

        #pragma unroll
        for (int j = 0; j < 8; ++j) {
            const uint32_t off0 = (uint32_t)((ko + 8 * j + g) * KPITCH + 4 * tq);
            #pragma unroll
            for (int s = 0; s < 4; ++s) {
                uint32_t o   = off0 + s * 32;
                uint32_t bh0 = lds32(aH + o), bh1 = lds32(aH + o + 16);
                uint32_t bl0 = lds32(aL + o), bl1 = lds32(aL + o + 16);
                mma16816(sacc[0][j], qa[0][0][s], bh0, bh1);   // Qh*Kh
                mma16816(sacc[1][j], qa[0][1][s], bh0, bh1);
                mma16816(sacc[0][j], qa[1][0][s], bh0, bh1);   // Ql*Kh
                mma16816(sacc[1][j], qa[1][1][s], bh0, bh1);
                mma16816(sacc[0][j], qa[0][0][s], bl0, bl1);   // Qh*Kl
                mma16816(sacc[1][j], qa[0][1][s], bl0, bl1);
            }
        }

        // ---- softmax (static max) + split-pack P into A-frags ----
        uint32_t pah[2][4][4], pal[2][4][4];
        #pragma unroll
        for (int mi = 0; mi < 2; ++mi)
            #pragma unroll
            for (int j = 0; j < 8; ++j) {
                float p0 = ex2(fmaf(sacc[mi][j][0], LOG2E, -mk[mi][0]));
                float p1 = ex2(fmaf(sacc[mi][j][1], LOG2E, -mk[mi][0]));
                float p2 = ex2(fmaf(sacc[mi][j][2], LOG2E, -mk[mi][1]));
                float p3 = ex2(fmaf(sacc[mi][j][3], LOG2E, -mk[mi][1]));
                lsum[mi][0] += p0 + p1;
                lsum[mi][1] += p2 + p3;
                uint32_t hp01, lp01, hp23, lp23;
                split2(p0, p1, hp01, lp01);
                split2(p2, p3, hp23, lp23);
                const int s2 = j >> 1, r = (j & 1) * 2;
                pah[mi][s2][r]     = hp01;
                pah[mi][s2][r + 1] = hp23;
                pal[mi][s2][r]     = lp01;
                pal[mi][s2][r + 1] = lp23;
            }

        // ---- O += P.K over this warp's 64-key slice (ldmatrix.trans V) ----
        #pragma unroll
        for (int s2 = 0; s2 < 4; ++s2) {
            const uint32_t base = (uint32_t)((ko + 16 * s2) * KPITCH) + laneoff;
            #pragma unroll
            for (int jp = 0; jp < 4; ++jp) {
                uint32_t bh[4], bl[4];
                ldsm4t(bh, aH + base + jp * 32);
                ldsm4t(bl, aL + base + jp * 32);
                #pragma unroll
                for (int mi = 0; mi < 2; ++mi) {
                    mma16816(oacc[mi][2 * jp],     pah[mi][s2], bh[0], bh[1]);  // Ph*Vh
                    mma16816(oacc[mi][2 * jp + 1], pah[mi][s2], bh[2], bh[3]);
                    mma16816(oacc[mi][2 * jp],     pal[mi][s2], bh[0], bh[1]);  // Pl*Vh
                    mma16816(oacc[mi][2 * jp + 1], pal[mi][s2], bh[2], bh[3]);
                    mma16816(oacc[mi][2 * jp],     pah[mi][s2], bl[0], bl[1]);  // Ph*Vl
                    mma16816(oacc[mi][2 * jp + 1], pah[mi][s2], bl[2], bl[3]);
                }
            }
        }
    }

    // ---- epilogue: reduce lsum over quad, combine 2 k-warps, normalize ----
    #pragma unroll
    for (int mi = 0; mi < 2; ++mi)
        #pragma unroll
        for (int h = 0; h < 2; ++h) {
            lsum[mi][h] += __shfl_xor_sync(0xffffffffu, lsum[mi][h], 1);
            lsum[mi][h] += __shfl_xor_sync(0xffffffffu, lsum[mi][h], 2);
        }

    float* redO = (float*)smem;                    // [4 qi][32 lanes][68]  (buf0)
    float* redL = (float*)(smem + 34816);          // [128] row lsums       (buf0 tail)
    float* stg  = (float*)(smem + 36864);          // [64 c][132 q]         (buf1)

    if (kj == 1) {
        float* dst = redO + qi * 2176 + lane * 68;
        #pragma unroll
        for (int mi = 0; mi < 2; ++mi)
            #pragma unroll
            for (int n = 0; n < 8; ++n)
                #pragma unroll
                for (int r = 0; r < 4; ++r)
                    dst[(mi * 8 + n) * 4 + r] = oacc[mi][n][r];
        if (tq == 0) {
            #pragma unroll
            for (int mi = 0; mi < 2; ++mi)
                #pragma unroll
                for (int h = 0; h < 2; ++h)
                    redL[qi * 32 + 16 * mi + 8 * h + g] = lsum[mi][h];
        }
    }
    __syncthreads();

    if (kj == 0) {
        const float* src = redO + qi * 2176 + lane * 68;
        float inv[2][2];
        #pragma unroll
        for (int mi = 0; mi < 2; ++mi)
            #pragma unroll
            for (int h = 0; h < 2; ++h)
                inv[mi][h] = 1.f / (lsum[mi][h] + redL[qi * 32 + 16 * mi + 8 * h + g]);
        #pragma unroll
        for (int mi = 0; mi < 2; ++mi)
            #pragma unroll
            for (int n = 0; n < 8; ++n)
                #pragma unroll
                for (int r = 0; r < 4; ++r) {
                    float v = (oacc[mi][n][r] + src[(mi * 8 + n) * 4 + r]) * inv[mi][r >> 1];
                    int q = qo + 16 * mi + g + ((r & 2) ? 8 : 0);
                    int c = 8 * n + 2 * tq + (r & 1);
                    stg[c * 132 + q] = v;
                }
    }
    __syncthreads();

    float* ob = out + (size_t)b * CCH * PPIX;
    #pragma unroll
    for (int it = 0; it < 8; ++it) {
        int i = t + 256 * it;
        int row = i >> 5, f4 = i & 31;
        float4 v = *(const float4*)(stg + row * 132 + f4 * 4);
        *(float4*)(ob + row * PPIX + q0 + 4 * f4) = v;
    }
}

// ---------------------------------------------------------------------------
extern "C" void kernel_launch(void* const* d_in, const int* in_sizes, int n_in,
                              void* d_out, int out_size) {
    const float* f = (const float*)d_in[0];   // foreground [4,64,64,64] fp32
    float* out = (float*)d_out;               // [4,64,64,64] fp32

    prep_kernel<<<dim3(16, 4), 256>>>(f);

    cudaFuncSetAttribute(attn_kernel, cudaFuncAttributeMaxDynamicSharedMemorySize, SMEM_TOTAL);
    attn_kernel<<<dim3(32, 4), 256, SMEM_TOTAL>>>(out);
}

// round 4
// speedup vs baseline: 3.5582x; 1.4801x over previous
#include <cuda_runtime.h>
#include <cuda_bf16.h>
#include <stdint.h>
#include <math.h>

// Problem constants: B=4, C=64, H=W=64, P=4096.
#define BATCH 4
#define CCH   64
#define PPIX  4096
#define LOG2E 1.4426950408889634f

// ---------------------------------------------------------------------------
// Device scratch (no allocation allowed). Split bf16: x = hi + lo (~16 bits).
// ---------------------------------------------------------------------------
__device__ __nv_bfloat16 g_Qh[BATCH * PPIX * CCH];  // Y boxsum  [b][p][c]
__device__ __nv_bfloat16 g_Ql[BATCH * PPIX * CCH];
__device__ __nv_bfloat16 g_Kh[BATCH * PPIX * CCH];  // K-hat     [b][p][c]
__device__ __nv_bfloat16 g_Kl[BATCH * PPIX * CCH];
__device__ float         g_m [BATCH * PPIX];        // |Y_q| (softmax max bound)

// ---------------------------------------------------------------------------
// helpers (baseline PTX only: mma.sync / ldmatrix / cp.async — no "a" features)
// ---------------------------------------------------------------------------
__device__ __forceinline__ uint32_t smem_u32(const void* p) {
    uint32_t a;
    asm("{ .reg .u64 t; cvta.to.shared.u64 t, %1; cvt.u32.u64 %0, t; }" : "=r"(a) : "l"(p));
    return a;
}
__device__ __forceinline__ uint32_t lds32(uint32_t a) {
    uint32_t v; asm volatile("ld.shared.b32 %0, [%1];" : "=r"(v) : "r"(a)); return v;
}
__device__ __forceinline__ void ldsm4t(uint32_t* r, uint32_t addr) {
    asm volatile("ldmatrix.sync.aligned.m8n8.x4.trans.shared.b16 {%0,%1,%2,%3}, [%4];"
        : "=r"(r[0]), "=r"(r[1]), "=r"(r[2]), "=r"(r[3]) : "r"(addr));
}
__device__ __forceinline__ void mma16816(float* d, const uint32_t* a, uint32_t b0, uint32_t b1) {
    asm volatile(
        "mma.sync.aligned.m16n8k16.row.col.f32.bf16.bf16.f32 "
        "{%0,%1,%2,%3}, {%4,%5,%6,%7}, {%8,%9}, {%0,%1,%2,%3};"
        : "+f"(d[0]), "+f"(d[1]), "+f"(d[2]), "+f"(d[3])
        : "r"(a[0]), "r"(a[1]), "r"(a[2]), "r"(a[3]), "r"(b0), "r"(b1));
}
__device__ __forceinline__ float ex2(float x) {
    float r; asm("ex2.approx.ftz.f32 %0, %1;" : "=f"(r) : "f"(x)); return r;
}
__device__ __forceinline__ void split_bf16(float x, __nv_bfloat16& h, __nv_bfloat16& l) {
    h = __float2bfloat16_rn(x);
    l = __float2bfloat16_rn(x - __bfloat162float(h));
}
__device__ __forceinline__ void split2(float p0, float p1, uint32_t& hp, uint32_t& lp) {
    __nv_bfloat16 h0, l0, h1, l1;
    split_bf16(p0, h0, l0);
    split_bf16(p1, h1, l1);
    hp = (uint32_t)__bfloat16_as_ushort(h0) | ((uint32_t)__bfloat16_as_ushort(h1) << 16);
    lp = (uint32_t)__bfloat16_as_ushort(l0) | ((uint32_t)__bfloat16_as_ushort(l1) << 16);
}

// K tile smem geometry: [128 k][64 c] bf16, row pitch 144B (128B data + 16B pad)
#define KPITCH    144
#define TILE_H    18432            // 128 * 144
#define BUF_BYTES 36864            // hi + lo
#define SMEM_TOTAL 73728           // two buffers

__device__ __forceinline__ void load_tile(uint32_t dbuf,
                                          const __nv_bfloat16* gKh,
                                          const __nv_bfloat16* gKl,
                                          int k0, int t) {
    #pragma unroll
    for (int c = 0; c < 4; ++c) {
        int idx = t + 256 * c;                 // 0..1023
        int row = idx >> 3, ch = idx & 7;
        uint32_t d = dbuf + row * KPITCH + ch * 16;
        const void* sh = gKh + (size_t)(k0 + row) * CCH + ch * 8;
        const void* sl = gKl + (size_t)(k0 + row) * CCH + ch * 8;
        asm volatile("cp.async.cg.shared.global [%0], [%1], 16;" :: "r"(d), "l"(sh));
        asm volatile("cp.async.cg.shared.global [%0], [%1], 16;" :: "r"(d + TILE_H), "l"(sl));
    }
}

// ---------------------------------------------------------------------------
// prep v2: one CTA per (h row, batch). Stage 3 input rows in smem, compute
// vertical 3-sums once, reduce channel norms via a small smem tree, and emit
// all bf16 arrays with coalesced [p][c] stores. 2 barriers total (not 128).
// ---------------------------------------------------------------------------
#define VPITCH 67
__global__ void __launch_bounds__(256) prep_kernel(const float* __restrict__ f) {
    const int b = blockIdx.y;
    const int h = blockIdx.x;
    const int t = threadIdx.x;

    __shared__ float vs[CCH * VPITCH];   // vertical 3-sum, col w+1, zero pad cols 0,65
    __shared__ float fs[CCH * VPITCH];   // center row
    __shared__ float rf[4][64], ry[4][64];
    __shared__ float sinv[64];

    const float* fb = f + (size_t)b * CCH * PPIX + h * 64;

    // Phase 1: load rows h-1,h,h+1 for all (c,w); coalesced along w.
    #pragma unroll
    for (int i = t; i < CCH * 64; i += 256) {
        int c = i >> 6, w = i & 63;
        const float* base = fb + (size_t)c * PPIX + w;
        float mid = base[0];
        float top = (h > 0)  ? base[-64] : 0.f;
        float bot = (h < 63) ? base[64]  : 0.f;
        vs[c * VPITCH + w + 1] = top + mid + bot;
        fs[c * VPITCH + w + 1] = mid;
    }
    if (t < CCH) { vs[t * VPITCH] = 0.f; vs[t * VPITCH + 65] = 0.f; }
    __syncthreads();

    // Phase 2: per-pixel channel reductions (4 partial lanes per w).
    {
        const int w = t & 63, s = t >> 6;
        float fsq = 0.f, ysq = 0.f;
        #pragma unroll
        for (int cc = 0; cc < 16; ++cc) {
            int c = s * 16 + cc;
            float fv = fs[c * VPITCH + w + 1];
            float yv = vs[c * VPITCH + w] + vs[c * VPITCH + w + 1] + vs[c * VPITCH + w + 2];
            fsq = fmaf(fv, fv, fsq);
            ysq = fmaf(yv, yv, ysq);
        }
        rf[s][w] = fsq;
        ry[s][w] = ysq;
    }
    __syncthreads();
    if (t < 64) {
        float F = rf[0][t] + rf[1][t] + rf[2][t] + rf[3][t];
        float Y = ry[0][t] + ry[1][t] + ry[2][t] + ry[3][t];
        sinv[t] = 1.f / (sqrtf(F) + 1e-8f);
        g_m[b * PPIX + h * 64 + t] = sqrtf(Y);
    }
    __syncthreads();

    // Phase 3: emit Q/K hi-lo splits; 64 consecutive c per w -> coalesced 2B stores.
    const int c = t & 63, s = t >> 6;
    #pragma unroll
    for (int it = 0; it < 16; ++it) {
        const int w = s * 16 + it;
        const float yv = vs[c * VPITCH + w] + vs[c * VPITCH + w + 1] + vs[c * VPITCH + w + 2];
        const float kv = fs[c * VPITCH + w + 1] * sinv[w];
        const size_t rowbase = ((size_t)(b * PPIX + h * 64 + w)) * CCH + c;
        __nv_bfloat16 hh, ll;
        split_bf16(yv, hh, ll);
        g_Qh[rowbase] = hh; g_Ql[rowbase] = ll;
        split_bf16(kv, hh, ll);
        g_Kh[rowbase] = hh; g_Kl[rowbase] = ll;
    }
}

// ---------------------------------------------------------------------------
// attn: CTA = (128-q tile, batch), 256 threads = 8 warps as 4(q) x 2(k-split).
// Per key tile of 128: S = Q.K^T (3 split MMAs), p = exp2(S*log2e - m*log2e)
// with static max m=|Y| (no online rescale), O += P.K (3 split MMAs) with the
// P C-frag -> A-frag register identity. lsum/O reduced across the 2 k-warps
// only in the epilogue.
// ---------------------------------------------------------------------------
__global__ void __launch_bounds__(256, 1) attn_kernel(float* __restrict__ out) {
    extern __shared__ char smem[];
    const uint32_t sb = smem_u32(smem);

    const int b    = blockIdx.y;
    const int q0   = blockIdx.x * 128;
    const int t    = threadIdx.x;
    const int lane = t & 31;
    const int wid  = t >> 5;
    const int qi   = wid >> 1, kj = wid & 1;
    const int qo   = qi * 32,  ko = kj * 64;
    const int g    = lane >> 2, tq = lane & 3;

    // ---- persistent Q A-frags (hi/lo) + per-row max bounds ----
    uint32_t qa[2][2][4][4];
    #pragma unroll
    for (int hl = 0; hl < 2; ++hl) {
        const __nv_bfloat16* Qsrc = hl ? g_Ql : g_Qh;
        #pragma unroll
        for (int mi = 0; mi < 2; ++mi) {
            const __nv_bfloat16* r0 = Qsrc + (size_t)(b * PPIX + q0 + qo + 16 * mi + g) * CCH;
            const __nv_bfloat16* r8 = r0 + 8 * CCH;
            #pragma unroll
            for (int s = 0; s < 4; ++s) {
                int c0 = 16 * s + 2 * tq;
                qa[hl][mi][s][0] = *(const uint32_t*)(r0 + c0);
                qa[hl][mi][s][1] = *(const uint32_t*)(r8 + c0);
                qa[hl][mi][s][2] = *(const uint32_t*)(r0 + c0 + 8);
                qa[hl][mi][s][3] = *(const uint32_t*)(r8 + c0 + 8);
            }
        }
    }
    float mk[2][2];
    #pragma unroll
    for (int mi = 0; mi < 2; ++mi)
        #pragma unroll
        for (int h = 0; h < 2; ++h)
            mk[mi][h] = g_m[b * PPIX + q0 + qo + 16 * mi + 8 * h + g] * LOG2E;

    float oacc[2][8][4];
    #pragma unroll
    for (int mi = 0; mi < 2; ++mi)
        #pragma unroll
        for (int n = 0; n < 8; ++n)
            #pragma unroll
            for (int r = 0; r < 4; ++r) oacc[mi][n][r] = 0.f;
    float lsum[2][2] = {{0.f, 0.f}, {0.f, 0.f}};

    const __nv_bfloat16* gKh = g_Kh + (size_t)b * PPIX * CCH;
    const __nv_bfloat16* gKl = g_Kl + (size_t)b * PPIX * CCH;

    // prefetch tile 0
    load_tile(sb, gKh, gKl, 0, t);
    asm volatile("cp.async.commit_group;" ::: "memory");

    const uint32_t laneoff = (uint32_t)(((lane & 7) + 8 * ((lane >> 3) & 1)) * KPITCH
                                        + (lane >> 4) * 16);

    for (int kt = 0; kt < 32; ++kt) {
        __syncthreads();                                  // frees buf[(kt+1)&1]
        if (kt + 1 < 32)
            load_tile(sb + ((kt + 1) & 1) * BUF_BYTES, gKh, gKl, (kt + 1) * 128, t);
        asm volatile("cp.async.commit_group;" ::: "memory");
        asm volatile("cp.async.wait_group 1;" ::: "memory");
        __syncthreads();                                  // buf[kt&1] visible

        const uint32_t aH = sb + (uint32_t)(kt & 1) * BUF_BYTES;
        const uint32_t aL = aH + TILE_H;

        // ---- S = Q.K^T over this warp's 64-key slice ----
        float sacc[2][8][4];
        #pragma unroll
        for (int mi = 0; mi < 2; ++mi)
            #pragma unroll
            for (int j = 0; j < 8; ++j)
                #pragma unroll
                for (int r = 0; r < 4; ++r) sacc[mi][j][r] = 0.f;

        #pragma unroll
        for (int j = 0; j < 8; ++j) {
            const uint32_t off0 = (uint32_t)((ko + 8 * j + g) * KPITCH + 4 * tq);
            #pragma unroll
            for (int s = 0; s < 4; ++s) {
                uint32_t o   = off0 + s * 32;
                uint32_t bh0 = lds32(aH + o), bh1 = lds32(aH + o + 16);
                uint32_t bl0 = lds32(aL + o), bl1 = lds32(aL + o + 16);
                mma16816(sacc[0][j], qa[0][0][s], bh0, bh1);   // Qh*Kh
                mma16816(sacc[1][j], qa[0][1][s], bh0, bh1);
                mma16816(sacc[0][j], qa[1][0][s], bh0, bh1);   // Ql*Kh
                mma16816(sacc[1][j], qa[1][1][s], bh0, bh1);
                mma16816(sacc[0][j], qa[0][0][s], bl0, bl1);   // Qh*Kl
                mma16816(sacc[1][j], qa[0][1][s], bl0, bl1);
            }
        }

        // ---- softmax (static max) + split-pack P into A-frags ----
        uint32_t pah[2][4][4], pal[2][4][4];
        #pragma unroll
        for (int mi = 0; mi < 2; ++mi)
            #pragma unroll
            for (int j = 0; j < 8; ++j) {
                float p0 = ex2(fmaf(sacc[mi][j][0], LOG2E, -mk[mi][0]));
                float p1 = ex2(fmaf(sacc[mi][j][1], LOG2E, -mk[mi][0]));
                float p2 = ex2(fmaf(sacc[mi][j][2], LOG2E, -mk[mi][1]));
                float p3 = ex2(fmaf(sacc[mi][j][3], LOG2E, -mk[mi][1]));
                lsum[mi][0] += p0 + p1;
                lsum[mi][1] += p2 + p3;
                uint32_t hp01, lp01, hp23, lp23;
                split2(p0, p1, hp01, lp01);
                split2(p2, p3, hp23, lp23);
                const int s2 = j >> 1, r = (j & 1) * 2;
                pah[mi][s2][r]     = hp01;
                pah[mi][s2][r + 1] = hp23;
                pal[mi][s2][r]     = lp01;
                pal[mi][s2][r + 1] = lp23;
            }

        // ---- O += P.K over this warp's 64-key slice (ldmatrix.trans V) ----
        #pragma unroll
        for (int s2 = 0; s2 < 4; ++s2) {
            const uint32_t base = (uint32_t)((ko + 16 * s2) * KPITCH) + laneoff;
            #pragma unroll
            for (int jp = 0; jp < 4; ++jp) {
                uint32_t bh[4], bl[4];
                ldsm4t(bh, aH + base + jp * 32);
                ldsm4t(bl, aL + base + jp * 32);
                #pragma unroll
                for (int mi = 0; mi < 2; ++mi) {
                    mma16816(oacc[mi][2 * jp],     pah[mi][s2], bh[0], bh[1]);  // Ph*Vh
                    mma16816(oacc[mi][2 * jp + 1], pah[mi][s2], bh[2], bh[3]);
                    mma16816(oacc[mi][2 * jp],     pal[mi][s2], bh[0], bh[1]);  // Pl*Vh
                    mma16816(oacc[mi][2 * jp + 1], pal[mi][s2], bh[2], bh[3]);
                    mma16816(oacc[mi][2 * jp],     pah[mi][s2], bl[0], bl[1]);  // Ph*Vl
                    mma16816(oacc[mi][2 * jp + 1], pah[mi][s2], bl[2], bl[3]);
                }
            }
        }
    }

    // ---- epilogue: reduce lsum over quad, combine 2 k-warps, normalize ----
    #pragma unroll
    for (int mi = 0; mi < 2; ++mi)
        #pragma unroll
        for (int h = 0; h < 2; ++h) {
            lsum[mi][h] += __shfl_xor_sync(0xffffffffu, lsum[mi][h], 1);
            lsum[mi][h] += __shfl_xor_sync(0xffffffffu, lsum[mi][h], 2);
        }

    float* redO = (float*)smem;                    // [4 qi][32 lanes][68]  (buf0)
    float* redL = (float*)(smem + 34816);          // [128] row lsums       (buf0 tail)
    float* stg  = (float*)(smem + 36864);          // [64 c][132 q]         (buf1)

    if (kj == 1) {
        float* dst = redO + qi * 2176 + lane * 68;
        #pragma unroll
        for (int mi = 0; mi < 2; ++mi)
            #pragma unroll
            for (int n = 0; n < 8; ++n)
                #pragma unroll
                for (int r = 0; r < 4; ++r)
                    dst[(mi * 8 + n) * 4 + r] = oacc[mi][n][r];
        if (tq == 0) {
            #pragma unroll
            for (int mi = 0; mi < 2; ++mi)
                #pragma unroll
                for (int h = 0; h < 2; ++h)
                    redL[qi * 32 + 16 * mi + 8 * h + g] = lsum[mi][h];
        }
    }
    __syncthreads();

    if (kj == 0) {
        const float* src = redO + qi * 2176 + lane * 68;
        float inv[2][2];
        #pragma unroll
        for (int mi = 0; mi < 2; ++mi)
            #pragma unroll
            for (int h = 0; h < 2; ++h)
                inv[mi][h] = 1.f / (lsum[mi][h] + redL[qi * 32 + 16 * mi + 8 * h + g]);
        #pragma unroll
        for (int mi = 0; mi < 2; ++mi)
            #pragma unroll
            for (int n = 0; n < 8; ++n)
                #pragma unroll
                for (int r = 0; r < 4; ++r) {
                    float v = (oacc[mi][n][r] + src[(mi * 8 + n) * 4 + r]) * inv[mi][r >> 1];
                    int q = qo + 16 * mi + g + ((r & 2) ? 8 : 0);
                    int c = 8 * n + 2 * tq + (r & 1);
                    stg[c * 132 + q] = v;
                }
    }
    __syncthreads();

    float* ob = out + (size_t)b * CCH * PPIX;
    #pragma unroll
    for (int it = 0; it < 8; ++it) {
        int i = t + 256 * it;
        int row = i >> 5, f4 = i & 31;
        float4 v = *(const float4*)(stg + row * 132 + f4 * 4);
        *(float4*)(ob + row * PPIX + q0 + 4 * f4) = v;
    }
}

// ---------------------------------------------------------------------------
extern "C" void kernel_launch(void* const* d_in, const int* in_sizes, int n_in,
                              void* d_out, int out_size) {
    const float* f = (const float*)d_in[0];   // foreground [4,64,64,64] fp32
    float* out = (float*)d_out;               // [4,64,64,64] fp32

    prep_kernel<<<dim3(64, 4), 256>>>(f);

    cudaFuncSetAttribute(attn_kernel, cudaFuncAttributeMaxDynamicSharedMemorySize, SMEM_TOTAL);
    attn_kernel<<<dim3(32, 4), 256, SMEM_TOTAL>>>(out);
}